// round 15
// baseline (speedup 1.0000x reference)
#include <cuda_runtime.h>
#include <cuda_bf16.h>
#include <math.h>
#include <stdint.h>

// ---------------- problem constants ----------------
#define D_     384
#define H_     6
#define HD_    64
#define L_     4
#define B_     8
#define N_     1024
#define SEQ_   1025
#define ROWS_  (B_*SEQ_)     // 8200
#define ROWSP_ 8320          // padded: no M predicates in weight GEMMs
#define NC_    2
#define QKV_N  (3*D_)        // 1152
#define FF_    (4*D_)        // 1536
#define SP_    1152          // padded seq (9*128)

typedef unsigned long long u64;
typedef unsigned int u32;

__device__ __forceinline__ float f2tf32(float f) {
    u32 u; asm("cvt.rna.tf32.f32 %0, %1;" : "=r"(u) : "f"(f));
    return __uint_as_float(u);
}

#define MMA_TF32(c, a, b) \
    asm("mma.sync.aligned.m16n8k8.row.col.f32.tf32.tf32.f32 " \
        "{%0,%1,%2,%3}, {%4,%5,%6,%7}, {%8,%9}, {%0,%1,%2,%3};" \
        : "+f"(c[0]), "+f"(c[1]), "+f"(c[2]), "+f"(c[3]) \
        : "r"(a[0]), "r"(a[1]), "r"(a[2]), "r"(a[3]), "r"(b[0]), "r"(b[1]))

#define CP16(saddr, gptr) \
    asm volatile("cp.async.ca.shared.global [%0], [%1], 16;" :: "r"(saddr), "l"(gptr))
#define CP_COMMIT() asm volatile("cp.async.commit_group;" ::: "memory")
#define CP_WAIT0()  asm volatile("cp.async.wait_group 0;" ::: "memory")
#define CP_WAIT1()  asm volatile("cp.async.wait_group 1;" ::: "memory")

__device__ __forceinline__ u32 smem_u32(const void* p) {
    u32 a;
    asm("{ .reg .u64 t; cvta.to.shared.u64 t, %1; cvt.u32.u64 %0, t; }" : "=r"(a) : "l"(p));
    return a;
}

// ---------------- scratch (device globals; no allocation allowed) ----------
__device__ float g_x[ROWSP_*D_];
__device__ float g_h[ROWSP_*D_];
__device__ float g_qkv[ROWSP_*QKV_N];
__device__ float g_attn[ROWSP_*D_];
__device__ float g_mlp[ROWSP_*FF_];
__device__ float g_pb[L_*QKV_N];
__device__ float g_qkvT[L_*QKV_N*D_];
__device__ float g_woT[L_*D_*D_];
__device__ float g_w1T[L_*FF_*D_];
__device__ float g_w2T[L_*D_*FF_];
__device__ float g_patT[D_*256];
__device__ float g_img[B_*N_*256];

// ---------------- GEMM v4.3 (tf32 mma, 128 thr, 3-stage cp.async) ------------
#define EPI_BIAS 0
#define EPI_RES  1
#define EPI_GELU 2
#define EPI_RND  3
#define EPI_PE   4
#define SSTRIDE 36
#define SBUF    (128*SSTRIDE)

__device__ __forceinline__ float gelu_f(float v) {
    return 0.5f * v * (1.f + erff(v * 0.70710678118654752f));
}

template<int EPI>
__global__ __launch_bounds__(128, 2)
void gemm4_k(const float* __restrict__ A, const float* __restrict__ Bm,
             const float* __restrict__ bias, const float* __restrict__ res,
             float* __restrict__ C, int M, int N, int K)
{
    extern __shared__ float sm[];
    // layout: A0 | A1 | A2 | B0 | B1 | B2, each SBUF floats
    const int tid  = threadIdx.x;
    const int lane = tid & 31, wid = tid >> 5;
    const int wm = (wid >> 1) * 64, wn = (wid & 1) * 64;
    const int g = lane >> 2, t = lane & 3;
    const size_t row0 = (size_t)blockIdx.y * 128;
    const size_t col0 = (size_t)blockIdx.x * 128;

    const int lr = tid >> 3;
    const int lk = (tid & 7) * 4;

    const float* Aptr = A + (row0 + lr) * K + lk;
    const float* Bptr = Bm + (col0 + lr) * K + lk;
    const u32 asb0 = smem_u32(sm);
    const u32 dst_off = (u32)(lr * SSTRIDE + lk) * 4;

    float c[4][8][4];
    #pragma unroll
    for (int i = 0; i < 4; i++)
        #pragma unroll
        for (int j = 0; j < 8; j++)
            #pragma unroll
            for (int f = 0; f < 4; f++) c[i][j][f] = 0.f;

    const int KT = K >> 5;

    // prologue: prefetch tiles 0 and 1
    #pragma unroll
    for (int s = 0; s < 2; s++) {
        if (s < KT) {
            int k0 = s << 5;
            u32 ad = asb0 + s*SBUF*4 + dst_off;
            u32 bd = asb0 + (3 + s)*SBUF*4 + dst_off;
            #pragma unroll
            for (int it = 0; it < 8; it++) {
                CP16(ad + it*16*SSTRIDE*4, Aptr + k0 + (size_t)it*16*K);
                CP16(bd + it*16*SSTRIDE*4, Bptr + k0 + (size_t)it*16*K);
            }
            CP_COMMIT();
        }
    }

    for (int kt = 0; kt < KT; kt++) {
        if (kt + 1 < KT) { CP_WAIT1(); } else { CP_WAIT0(); }
        __syncthreads();
        if (kt + 2 < KT) {
            int bi = (kt + 2) % 3;
            int k0 = (kt + 2) << 5;
            u32 ad = asb0 + bi*SBUF*4 + dst_off;
            u32 bd = asb0 + (3 + bi)*SBUF*4 + dst_off;
            #pragma unroll
            for (int it = 0; it < 8; it++) {
                CP16(ad + it*16*SSTRIDE*4, Aptr + k0 + (size_t)it*16*K);
                CP16(bd + it*16*SSTRIDE*4, Bptr + k0 + (size_t)it*16*K);
            }
            CP_COMMIT();
        }
        const int cb_ = kt % 3;
        const float* As_ = sm + cb_*SBUF;
        const float* Bs_ = sm + (3 + cb_)*SBUF;
        #pragma unroll
        for (int ks = 0; ks < 4; ks++) {
            const int k8 = ks * 8;
            u32 a[4][4], b[8][2];
            #pragma unroll
            for (int i = 0; i < 4; i++) {
                int m0 = wm + 16*i;
                a[i][0] = __float_as_uint(As_[(m0+g  )*SSTRIDE + k8 + t  ]);
                a[i][1] = __float_as_uint(As_[(m0+g+8)*SSTRIDE + k8 + t  ]);
                a[i][2] = __float_as_uint(As_[(m0+g  )*SSTRIDE + k8 + t+4]);
                a[i][3] = __float_as_uint(As_[(m0+g+8)*SSTRIDE + k8 + t+4]);
            }
            #pragma unroll
            for (int j = 0; j < 8; j++) {
                int n0 = wn + 8*j;
                b[j][0] = __float_as_uint(Bs_[(n0+g)*SSTRIDE + k8 + t  ]);
                b[j][1] = __float_as_uint(Bs_[(n0+g)*SSTRIDE + k8 + t+4]);
            }
            #pragma unroll
            for (int i = 0; i < 4; i++)
                #pragma unroll
                for (int j = 0; j < 8; j++)
                    MMA_TF32(c[i][j], a[i], b[j]);
        }
        // no trailing sync: next iteration's wait+sync orders buffer reuse
    }

    #pragma unroll
    for (int i = 0; i < 4; i++) {
        size_t r0 = row0 + wm + 16*i + g;
        size_t r1 = r0 + 8;
        #pragma unroll
        for (int j = 0; j < 8; j++) {
            int cb = (int)col0 + wn + 8*j + 2*t;
            float b0 = bias[cb], b1 = bias[cb+1];
            float v0 = c[i][j][0] + b0, v1 = c[i][j][1] + b1;
            float v2 = c[i][j][2] + b0, v3 = c[i][j][3] + b1;
            if (EPI == EPI_RES) {
                float2 ra = *(const float2*)&res[r0*N + cb];
                float2 rb = *(const float2*)&res[r1*N + cb];
                v0 += ra.x; v1 += ra.y; v2 += rb.x; v3 += rb.y;
            }
            if (EPI == EPI_GELU) {
                v0 = f2tf32(gelu_f(v0)); v1 = f2tf32(gelu_f(v1));
                v2 = f2tf32(gelu_f(v2)); v3 = f2tf32(gelu_f(v3));
            }
            if (EPI == EPI_RND) {
                v0 = f2tf32(v0); v1 = f2tf32(v1);
                v2 = f2tf32(v2); v3 = f2tf32(v3);
            }
            if (EPI == EPI_PE) {
                float f0 = __expf((float)(cb & ~1)  * (1.f/(float)D_) * -9.210340371976184f);
                float f1 = __expf((float)((cb+1)&~1)* (1.f/(float)D_) * -9.210340371976184f);
                {
                    int bb_ = (int)(r0 >> 10), nn = (int)(r0 & 1023);
                    float pos = (float)(nn + 1);
                    float s0, c0s, s1, c1s;
                    __sincosf(pos * f0, &s0, &c0s);
                    __sincosf(pos * f1, &s1, &c1s);
                    float pe0 = (cb & 1) ? c0s : s0;
                    float pe1 = ((cb+1) & 1) ? c1s : s1;
                    size_t o = ((size_t)bb_*SEQ_ + nn + 1)*D_ + cb;
                    *(float2*)&C[o] = make_float2(v0 + pe0, v1 + pe1);
                }
                {
                    int bb_ = (int)(r1 >> 10), nn = (int)(r1 & 1023);
                    float pos = (float)(nn + 1);
                    float s0, c0s, s1, c1s;
                    __sincosf(pos * f0, &s0, &c0s);
                    __sincosf(pos * f1, &s1, &c1s);
                    float pe0 = (cb & 1) ? c0s : s0;
                    float pe1 = ((cb+1) & 1) ? c1s : s1;
                    size_t o = ((size_t)bb_*SEQ_ + nn + 1)*D_ + cb;
                    *(float2*)&C[o] = make_float2(v2 + pe0, v3 + pe1);
                }
            } else {
                *(float2*)&C[r0*N + cb] = make_float2(v0, v1);
                *(float2*)&C[r1*N + cb] = make_float2(v2, v3);
            }
        }
    }
}

// ---------------- fused flash attention (double-buffered, occ 1) -------------
#define FS_STRIDE 68
#define FV_STRIDE 72
#define FK_OFF   (128*FS_STRIDE)
#define FK_TILE  (128*FS_STRIDE)
#define FV_OFF   (3*128*FS_STRIDE)
#define FV_TILE  (128*FV_STRIDE)
#define FS_TOTALF (3*128*FS_STRIDE + 2*128*FV_STRIDE)  // 44544 floats

__global__ __launch_bounds__(256, 1)
void flash_k(const float* __restrict__ qkv, float* __restrict__ attn)
{
    extern __shared__ float sm[];
    __shared__ float rsx[4][32];
    const int tid  = threadIdx.x;
    const int lane = tid & 31, wid = tid >> 5;
    const int wr = wid >> 1, wc = wid & 1;
    const int wm = wr*32, wn = wc*64;
    const int g = lane >> 2, t = lane & 3;
    const int q0 = blockIdx.x * 128;
    const int bh = blockIdx.y, b = bh / H_, h = bh % H_;
    const float* Qb = qkv + (size_t)b*SEQ_*QKV_N + h*HD_;
    const float* Kb = Qb + D_;
    const float* Vb = Qb + 2*D_;

    const int lr = tid >> 3;
    const int kc = (tid & 7) * 8;
    const u32 sb = smem_u32(sm);

    #pragma unroll
    for (int it = 0; it < 4; it++) {
        int r = lr + 32*it;
        int q = min(q0 + r, SEQ_-1);
        const float4* qa = (const float4*)(Qb + (size_t)q*QKV_N + kc);
        float4 a0 = qa[0], a1 = qa[1];
        a0.x *= 0.125f; a0.y *= 0.125f; a0.z *= 0.125f; a0.w *= 0.125f;
        a1.x *= 0.125f; a1.y *= 0.125f; a1.z *= 0.125f; a1.w *= 0.125f;
        *(float4*)(sm + r*FS_STRIDE + kc)     = a0;
        *(float4*)(sm + r*FS_STRIDE + kc + 4) = a1;
    }

    {
        #pragma unroll
        for (int it = 0; it < 4; it++) {
            int r = lr + 32*it;
            int j = min(r, SEQ_-1);
            u32 dK = (u32)(FK_OFF + r*FS_STRIDE + kc)*4;
            u32 dV = (u32)(FV_OFF + r*FV_STRIDE + kc)*4;
            CP16(sb + dK,      Kb + (size_t)j*QKV_N + kc);
            CP16(sb + dK + 16, Kb + (size_t)j*QKV_N + kc + 4);
            CP16(sb + dV,      Vb + (size_t)j*QKV_N + kc);
            CP16(sb + dV + 16, Vb + (size_t)j*QKV_N + kc + 4);
        }
        CP_COMMIT();
    }

    float c2[2][8][4];
    #pragma unroll
    for (int i = 0; i < 2; i++)
        #pragma unroll
        for (int j = 0; j < 8; j++)
            #pragma unroll
            for (int f = 0; f < 4; f++) c2[i][j][f] = 0.f;
    float rs[2][2] = {{0.f,0.f},{0.f,0.f}};

    int buf = 0;
    for (int kb = 0; kb < 9; kb++) {
        CP_WAIT0();
        __syncthreads();
        if (kb + 1 < 9) {
            int nb = buf ^ 1;
            #pragma unroll
            for (int it = 0; it < 4; it++) {
                int r = lr + 32*it;
                int j = min((kb+1)*128 + r, SEQ_-1);
                u32 dK = (u32)(FK_OFF + nb*FK_TILE + r*FS_STRIDE + kc)*4;
                u32 dV = (u32)(FV_OFF + nb*FV_TILE + r*FV_STRIDE + kc)*4;
                CP16(sb + dK,      Kb + (size_t)j*QKV_N + kc);
                CP16(sb + dK + 16, Kb + (size_t)j*QKV_N + kc + 4);
                CP16(sb + dV,      Vb + (size_t)j*QKV_N + kc);
                CP16(sb + dV + 16, Vb + (size_t)j*QKV_N + kc + 4);
            }
            CP_COMMIT();
        }

        const float* Ksb = sm + FK_OFF + buf*FK_TILE;
        const float* Vsb = sm + FV_OFF + buf*FV_TILE;

        float c[2][8][4];
        #pragma unroll
        for (int i = 0; i < 2; i++)
            #pragma unroll
            for (int j = 0; j < 8; j++)
                #pragma unroll
                for (int f = 0; f < 4; f++) c[i][j][f] = 0.f;

        #pragma unroll
        for (int ks = 0; ks < 8; ks++) {
            const int k8 = ks*8;
            u32 a[2][4], bb[8][2];
            #pragma unroll
            for (int i = 0; i < 2; i++) {
                int m0 = wm + 16*i;
                a[i][0] = __float_as_uint(sm[(m0+g  )*FS_STRIDE + k8 + t  ]);
                a[i][1] = __float_as_uint(sm[(m0+g+8)*FS_STRIDE + k8 + t  ]);
                a[i][2] = __float_as_uint(sm[(m0+g  )*FS_STRIDE + k8 + t+4]);
                a[i][3] = __float_as_uint(sm[(m0+g+8)*FS_STRIDE + k8 + t+4]);
            }
            #pragma unroll
            for (int j = 0; j < 8; j++) {
                int n0 = wn + 8*j;
                bb[j][0] = __float_as_uint(Ksb[(n0+g)*FS_STRIDE + k8 + t  ]);
                bb[j][1] = __float_as_uint(Ksb[(n0+g)*FS_STRIDE + k8 + t+4]);
            }
            #pragma unroll
            for (int i = 0; i < 2; i++)
                #pragma unroll
                for (int j = 0; j < 8; j++)
                    MMA_TF32(c[i][j], a[i], bb[j]);
        }

        #pragma unroll
        for (int i = 0; i < 2; i++) {
            #pragma unroll
            for (int j = 0; j < 8; j++) {
                int colb = kb*128 + wn + 8*j + 2*t;
                float p0 = (colb   < SEQ_) ? f2tf32(__expf(c[i][j][0])) : 0.f;
                float p1 = (colb+1 < SEQ_) ? f2tf32(__expf(c[i][j][1])) : 0.f;
                float p2 = (colb   < SEQ_) ? f2tf32(__expf(c[i][j][2])) : 0.f;
                float p3 = (colb+1 < SEQ_) ? f2tf32(__expf(c[i][j][3])) : 0.f;
                c[i][j][0] = p0; c[i][j][1] = p1; c[i][j][2] = p2; c[i][j][3] = p3;
                rs[i][0] += p0 + p1;
                rs[i][1] += p2 + p3;
            }
        }

        const int sL = (lane & ~3) | (t >> 1);
        const int sH = sL | 2;
        const bool odd = (t & 1);
        #pragma unroll
        for (int ks = 0; ks < 8; ks++) {
            u32 a2[2][4];
            #pragma unroll
            for (int i = 0; i < 2; i++) {
                float p0 = __shfl_sync(0xffffffffu, c[i][ks][0], sL);
                float p1 = __shfl_sync(0xffffffffu, c[i][ks][1], sL);
                float p2 = __shfl_sync(0xffffffffu, c[i][ks][2], sL);
                float p3 = __shfl_sync(0xffffffffu, c[i][ks][3], sL);
                float q0 = __shfl_sync(0xffffffffu, c[i][ks][0], sH);
                float q1 = __shfl_sync(0xffffffffu, c[i][ks][1], sH);
                float q2 = __shfl_sync(0xffffffffu, c[i][ks][2], sH);
                float q3 = __shfl_sync(0xffffffffu, c[i][ks][3], sH);
                a2[i][0] = __float_as_uint(odd ? p1 : p0);
                a2[i][1] = __float_as_uint(odd ? p3 : p2);
                a2[i][2] = __float_as_uint(odd ? q1 : q0);
                a2[i][3] = __float_as_uint(odd ? q3 : q2);
            }
            #pragma unroll
            for (int j = 0; j < 8; j++) {
                u32 bb[2];
                bb[0] = __float_as_uint(Vsb[(wn + ks*8 + t    )*FV_STRIDE + 8*j + g]);
                bb[1] = __float_as_uint(Vsb[(wn + ks*8 + t + 4)*FV_STRIDE + 8*j + g]);
                #pragma unroll
                for (int i = 0; i < 2; i++)
                    MMA_TF32(c2[i][j], a2[i], bb);
            }
        }
        buf ^= 1;
    }

    #pragma unroll
    for (int i = 0; i < 2; i++) {
        #pragma unroll
        for (int s = 0; s < 2; s++) {
            float v = rs[i][s];
            v += __shfl_xor_sync(0xffffffffu, v, 1);
            v += __shfl_xor_sync(0xffffffffu, v, 2);
            rs[i][s] = v;
        }
    }

    __syncthreads();
    if (wc == 1) {
        float* Ox = sm + wr*(32*FS_STRIDE);
        #pragma unroll
        for (int i = 0; i < 2; i++) {
            #pragma unroll
            for (int j = 0; j < 8; j++) {
                *(float2*)(Ox + (16*i+g  )*FS_STRIDE + 8*j + 2*t) = make_float2(c2[i][j][0], c2[i][j][1]);
                *(float2*)(Ox + (16*i+g+8)*FS_STRIDE + 8*j + 2*t) = make_float2(c2[i][j][2], c2[i][j][3]);
            }
        }
        if (t == 0) {
            rsx[wr][16*0+g]   = rs[0][0];
            rsx[wr][16*0+g+8] = rs[0][1];
            rsx[wr][16*1+g]   = rs[1][0];
            rsx[wr][16*1+g+8] = rs[1][1];
        }
    }
    __syncthreads();
    if (wc == 0) {
        const float* Ox = sm + wr*(32*FS_STRIDE);
        #pragma unroll
        for (int i = 0; i < 2; i++) {
            int r0 = q0 + wm + 16*i + g;
            int r1 = r0 + 8;
            float inv0 = 1.f / (rs[i][0] + rsx[wr][16*i+g]);
            float inv1 = 1.f / (rs[i][1] + rsx[wr][16*i+g+8]);
            #pragma unroll
            for (int j = 0; j < 8; j++) {
                float2 e0 = *(const float2*)(Ox + (16*i+g  )*FS_STRIDE + 8*j + 2*t);
                float2 e1 = *(const float2*)(Ox + (16*i+g+8)*FS_STRIDE + 8*j + 2*t);
                if (r0 < SEQ_) {
                    size_t o = ((size_t)b*SEQ_ + r0)*D_ + h*HD_ + 8*j + 2*t;
                    *(float2*)&attn[o] = make_float2(f2tf32((c2[i][j][0]+e0.x)*inv0),
                                                     f2tf32((c2[i][j][1]+e0.y)*inv0));
                }
                if (r1 < SEQ_) {
                    size_t o = ((size_t)b*SEQ_ + r1)*D_ + h*HD_ + 8*j + 2*t;
                    *(float2*)&attn[o] = make_float2(f2tf32((c2[i][j][2]+e1.x)*inv1),
                                                     f2tf32((c2[i][j][3]+e1.y)*inv1));
                }
            }
        }
    }
}

// ---------------- layernorm: warp per row, shfl reductions -------------------
__global__ __launch_bounds__(256)
void ln_k(const float* __restrict__ x, const float* __restrict__ g,
          const float* __restrict__ b, float* __restrict__ y)
{
    const int w    = threadIdx.x >> 5;
    const int lane = threadIdx.x & 31;
    const int row  = blockIdx.x * 8 + w;
    const float* xr = x + (size_t)row*D_;
    float v[12];
    float s = 0.f;
    #pragma unroll
    for (int i = 0; i < 12; i++) { v[i] = xr[lane + 32*i]; s += v[i]; }
    #pragma unroll
    for (int o = 16; o > 0; o >>= 1) s += __shfl_xor_sync(0xffffffffu, s, o);
    float mu = s * (1.f/D_);
    float s2 = 0.f;
    #pragma unroll
    for (int i = 0; i < 12; i++) { float d = v[i]-mu; s2 += d*d; }
    #pragma unroll
    for (int o = 16; o > 0; o >>= 1) s2 += __shfl_xor_sync(0xffffffffu, s2, o);
    float inv = rsqrtf(s2*(1.f/D_) + 1e-5f);
    float* yr = y + (size_t)row*D_;
    #pragma unroll
    for (int i = 0; i < 12; i++) {
        int c = lane + 32*i;
        yr[c] = f2tf32((v[i]-mu)*inv*g[c] + b[c]);
    }
}

// ---------------- all prep in ONE kernel (weights + image round + cls rows) --
#define T1_ (L_*QKV_N*D_)
#define T2_ (L_*D_*D_)
#define T3_ (L_*FF_*D_)
#define T4_ (L_*D_*FF_)
#define T5_ (D_*256)
#define T6_ (L_*QKV_N)
#define T7_ (B_*N_*256)
#define T8_ (B_*D_)
__global__ void prep_k(const float* __restrict__ wq, const float* __restrict__ wk,
                       const float* __restrict__ wv, const float* __restrict__ bq,
                       const float* __restrict__ bk, const float* __restrict__ bv,
                       const float* __restrict__ wo, const float* __restrict__ w1,
                       const float* __restrict__ w2, const float* __restrict__ pat,
                       const float* __restrict__ images, const float* __restrict__ cls,
                       float* __restrict__ qkvT, float* __restrict__ woT,
                       float* __restrict__ w1T, float* __restrict__ w2T,
                       float* __restrict__ patT, float* __restrict__ pb,
                       float* __restrict__ img, float* __restrict__ x)
{
    int idx = blockIdx.x*blockDim.x + threadIdx.x;
    if (idx < T1_) {
        int k = idx % D_; int r = idx / D_; int n = r % QKV_N; int l = r / QKV_N;
        int sec = n / D_, jj = n % D_, h = jj >> 6, e = jj & 63;
        const float* w = (sec == 0) ? wq : (sec == 1) ? wk : wv;
        qkvT[idx] = f2tf32(w[(((size_t)l*H_ + h)*D_ + k)*HD_ + e]);
    } else if (idx < T1_+T2_) {
        int i = idx - T1_;
        int k = i % D_; int r = i / D_; int n = r % D_; int l = r / D_;
        woT[i] = f2tf32(wo[((size_t)l*D_ + k)*D_ + n]);
    } else if (idx < T1_+T2_+T3_) {
        int i = idx - (T1_+T2_);
        int k = i % D_; int r = i / D_; int n = r % FF_; int l = r / FF_;
        w1T[i] = f2tf32(w1[((size_t)l*D_ + k)*FF_ + n]);
    } else if (idx < T1_+T2_+T3_+T4_) {
        int i = idx - (T1_+T2_+T3_);
        int k = i % FF_; int r = i / FF_; int n = r % D_; int l = r / D_;
        w2T[i] = f2tf32(w2[((size_t)l*FF_ + k)*D_ + n]);
    } else if (idx < T1_+T2_+T3_+T4_+T5_) {
        int i = idx - (T1_+T2_+T3_+T4_);
        int k = i % 256; int n = i / 256;
        patT[i] = f2tf32(pat[(size_t)k*D_ + n]);
    } else if (idx < T1_+T2_+T3_+T4_+T5_+T6_) {
        int i = idx - (T1_+T2_+T3_+T4_+T5_);
        int n = i % QKV_N; int l = i / QKV_N;
        int sec = n / D_, jj = n % D_, h = jj >> 6, e = jj & 63;
        const float* bb = (sec == 0) ? bq : (sec == 1) ? bk : bv;
        pb[i] = bb[((size_t)l*H_ + h)*HD_ + e];
    } else if (idx < T1_+T2_+T3_+T4_+T5_+T6_+T7_) {
        int i = idx - (T1_+T2_+T3_+T4_+T5_+T6_);
        img[i] = f2tf32(images[i]);
    } else if (idx < T1_+T2_+T3_+T4_+T5_+T6_+T7_+T8_) {
        int i = idx - (T1_+T2_+T3_+T4_+T5_+T6_+T7_);
        int d = i % D_; int b = i / D_;
        x[(size_t)b*SEQ_*D_ + d] = cls[d] + ((d & 1) ? 1.f : 0.f);
    }
}

// ---------------- fused head: logits (NC=2) + deconv upsample ----------------
__global__ __launch_bounds__(256)
void head_k(const float* __restrict__ x, const float* __restrict__ cw,
            const float* __restrict__ cb, const float* __restrict__ dw,
            const float* __restrict__ db, float* __restrict__ out)
{
    const int w    = threadIdx.x >> 5;
    const int lane = threadIdx.x & 31;
    const int tok  = blockIdx.x * 8 + w;
    const int b = tok >> 10, n = tok & 1023;
    const float* xr = x + ((size_t)b*SEQ_ + n + 1)*D_;

    float s0 = 0.f, s1 = 0.f;
    #pragma unroll
    for (int i = 0; i < 12; i++) {
        int d = lane + 32*i;
        float xv = xr[d];
        s0 += xv * cw[d*NC_];
        s1 += xv * cw[d*NC_ + 1];
    }
    #pragma unroll
    for (int o = 16; o > 0; o >>= 1) {
        s0 += __shfl_xor_sync(0xffffffffu, s0, o);
        s1 += __shfl_xor_sync(0xffffffffu, s1, o);
    }
    float z0 = s0 + cb[0], z1 = s1 + cb[1];

    #pragma unroll
    for (int o = 0; o < NC_; o++) {
        size_t base = ((size_t)(b*NC_ + o) * (N_*16) + n*16) * 16;
        float dbv = db[o];
        #pragma unroll
        for (int i = 0; i < 8; i++) {
            int p = lane + 32*i;
            out[base + p] = dbv + z0*dw[o*256 + p] + z1*dw[(NC_ + o)*256 + p];
        }
    }
}

// ---------------- launch ------------------------------------------------------
extern "C" void kernel_launch(void* const* d_in, const int* in_sizes, int n_in,
                              void* d_out, int out_size)
{
    const float* images  = (const float*)d_in[0];
    const float* patch_w = (const float*)d_in[2];
    const float* patch_b = (const float*)d_in[3];
    const float* cls_tok = (const float*)d_in[4];
    const float* ln1_g   = (const float*)d_in[5];
    const float* ln1_b   = (const float*)d_in[6];
    const float* wq      = (const float*)d_in[7];
    const float* bq      = (const float*)d_in[8];
    const float* wk      = (const float*)d_in[9];
    const float* bk      = (const float*)d_in[10];
    const float* wv      = (const float*)d_in[11];
    const float* bv      = (const float*)d_in[12];
    const float* wo      = (const float*)d_in[13];
    const float* bo      = (const float*)d_in[14];
    const float* ln2_g   = (const float*)d_in[15];
    const float* ln2_b   = (const float*)d_in[16];
    const float* w1      = (const float*)d_in[17];
    const float* b1      = (const float*)d_in[18];
    const float* w2      = (const float*)d_in[19];
    const float* b2      = (const float*)d_in[20];
    const float* cls_w   = (const float*)d_in[21];
    const float* cls_b   = (const float*)d_in[22];
    const float* dc_w    = (const float*)d_in[23];
    const float* dc_b    = (const float*)d_in[24];
    float* out = (float*)d_out;

    float *x, *h, *qkv, *attn, *mlp, *pb;
    float *qkvT, *woT, *w1T, *w2T, *patT, *img;
    cudaGetSymbolAddress((void**)&x,    g_x);
    cudaGetSymbolAddress((void**)&h,    g_h);
    cudaGetSymbolAddress((void**)&qkv,  g_qkv);
    cudaGetSymbolAddress((void**)&attn, g_attn);
    cudaGetSymbolAddress((void**)&mlp,  g_mlp);
    cudaGetSymbolAddress((void**)&pb,   g_pb);
    cudaGetSymbolAddress((void**)&qkvT, g_qkvT);
    cudaGetSymbolAddress((void**)&woT,  g_woT);
    cudaGetSymbolAddress((void**)&w1T,  g_w1T);
    cudaGetSymbolAddress((void**)&w2T,  g_w2T);
    cudaGetSymbolAddress((void**)&patT, g_patT);
    cudaGetSymbolAddress((void**)&img,  g_img);

    const int SMEM_G = 6*SBUF*4;            // gemm4: 110592 B (3-stage)
    const int SMEM_F = FS_TOTALF*4;         // flash: 178176 B
    cudaFuncSetAttribute(gemm4_k<EPI_BIAS>, cudaFuncAttributeMaxDynamicSharedMemorySize, SMEM_G);
    cudaFuncSetAttribute(gemm4_k<EPI_RES>,  cudaFuncAttributeMaxDynamicSharedMemorySize, SMEM_G);
    cudaFuncSetAttribute(gemm4_k<EPI_GELU>, cudaFuncAttributeMaxDynamicSharedMemorySize, SMEM_G);
    cudaFuncSetAttribute(gemm4_k<EPI_RND>,  cudaFuncAttributeMaxDynamicSharedMemorySize, SMEM_G);
    cudaFuncSetAttribute(gemm4_k<EPI_PE>,   cudaFuncAttributeMaxDynamicSharedMemorySize, SMEM_G);
    cudaFuncSetAttribute(flash_k, cudaFuncAttributeMaxDynamicSharedMemorySize, SMEM_F);

    {
        int total = T1_+T2_+T3_+T4_+T5_+T6_+T7_+T8_;
        prep_k<<<(total + 255)/256, 256>>>(wq, wk, wv, bq, bk, bv, wo, w1, w2,
                                           patch_w, images, cls_tok,
                                           qkvT, woT, w1T, w2T, patT, pb, img, x);
    }
    {
        dim3 g(D_/128, (B_*N_)/128);
        gemm4_k<EPI_PE><<<g, 128, SMEM_G>>>(img, patT, patch_b, nullptr, x,
                                            B_*N_, D_, 256);
    }

    dim3 gq(QKV_N/128, ROWSP_/128);
    dim3 go(D_/128,    ROWSP_/128);
    dim3 g1(FF_/128,   ROWSP_/128);
    dim3 gf(SP_/128, B_*H_);

    for (int l = 0; l < L_; l++) {
        ln_k<<<ROWS_/8, 256>>>(x, ln1_g + l*D_, ln1_b + l*D_, h);
        gemm4_k<EPI_RND><<<gq, 128, SMEM_G>>>(h, qkvT + (size_t)l*QKV_N*D_,
                                              pb + l*QKV_N, nullptr,
                                              qkv, ROWSP_, QKV_N, D_);
        flash_k<<<gf, 256, SMEM_F>>>(qkv, attn);
        gemm4_k<EPI_RES><<<go, 128, SMEM_G>>>(attn, woT + (size_t)l*D_*D_,
                                              bo + l*D_, x,
                                              x, ROWSP_, D_, D_);
        ln_k<<<ROWS_/8, 256>>>(x, ln2_g + l*D_, ln2_b + l*D_, h);
        gemm4_k<EPI_GELU><<<g1, 128, SMEM_G>>>(h, w1T + (size_t)l*FF_*D_,
                                               b1 + l*FF_, nullptr,
                                               mlp, ROWSP_, FF_, D_);
        gemm4_k<EPI_RES><<<go, 128, SMEM_G>>>(mlp, w2T + (size_t)l*D_*FF_,
                                              b2 + l*D_, x,
                                              x, ROWSP_, D_, FF_);
    }

    head_k<<<(B_*N_)/8, 256>>>(x, cls_w, cls_b, dc_w, dc_b, out);
    (void)in_sizes; (void)n_in; (void)out_size;
}

// round 16
// speedup vs baseline: 1.1351x; 1.1351x over previous
#include <cuda_runtime.h>
#include <cuda_bf16.h>
#include <math.h>
#include <stdint.h>

// ---------------- problem constants ----------------
#define D_     384
#define H_     6
#define HD_    64
#define L_     4
#define B_     8
#define N_     1024
#define SEQ_   1025
#define ROWS_  (B_*SEQ_)     // 8200
#define ROWSP_ 8320          // padded: no M predicates in weight GEMMs
#define NC_    2
#define QKV_N  (3*D_)        // 1152
#define FF_    (4*D_)        // 1536
#define SP_    1152          // padded seq (9*128)

typedef unsigned long long u64;
typedef unsigned int u32;

__device__ __forceinline__ float f2tf32(float f) {
    u32 u; asm("cvt.rna.tf32.f32 %0, %1;" : "=r"(u) : "f"(f));
    return __uint_as_float(u);
}

#define MMA_TF32(c, a, b) \
    asm("mma.sync.aligned.m16n8k8.row.col.f32.tf32.tf32.f32 " \
        "{%0,%1,%2,%3}, {%4,%5,%6,%7}, {%8,%9}, {%0,%1,%2,%3};" \
        : "+f"(c[0]), "+f"(c[1]), "+f"(c[2]), "+f"(c[3]) \
        : "r"(a[0]), "r"(a[1]), "r"(a[2]), "r"(a[3]), "r"(b[0]), "r"(b[1]))

#define CP16(saddr, gptr) \
    asm volatile("cp.async.ca.shared.global [%0], [%1], 16;" :: "r"(saddr), "l"(gptr))
#define CP_COMMIT() asm volatile("cp.async.commit_group;" ::: "memory")
#define CP_WAIT0()  asm volatile("cp.async.wait_group 0;" ::: "memory")

__device__ __forceinline__ u32 smem_u32(const void* p) {
    u32 a;
    asm("{ .reg .u64 t; cvta.to.shared.u64 t, %1; cvt.u32.u64 %0, t; }" : "=r"(a) : "l"(p));
    return a;
}

// ---------------- scratch (device globals; no allocation allowed) ----------
__device__ float g_x[ROWSP_*D_];
__device__ float g_h[ROWSP_*D_];
__device__ float g_qkv[ROWSP_*QKV_N];
__device__ float g_attn[ROWSP_*D_];
__device__ float g_mlp[ROWSP_*FF_];
__device__ float g_pb[L_*QKV_N];
__device__ float g_qkvT[L_*QKV_N*D_];
__device__ float g_woT[L_*D_*D_];
__device__ float g_w1T[L_*FF_*D_];
__device__ float g_w2T[L_*D_*FF_];
__device__ float g_patT[D_*256];
__device__ float g_img[B_*N_*256];

// ---------------- GEMM v4 (tf32 mma, 128 thr, 2-stage, tile 128 x TN) --------
#define EPI_BIAS 0
#define EPI_RES  1
#define EPI_GELU 2
#define EPI_RND  3
#define EPI_PE   4
#define SSTRIDE 36

__device__ __forceinline__ float gelu_f(float v) {
    return 0.5f * v * (1.f + erff(v * 0.70710678118654752f));
}

template<int EPI, int TN>
__global__ __launch_bounds__(128, 2)
void gemm4_k(const float* __restrict__ A, const float* __restrict__ Bm,
             const float* __restrict__ bias, const float* __restrict__ res,
             float* __restrict__ C, int M, int N, int K)
{
    extern __shared__ float sm[];
    constexpr int SBUF_A = 128*SSTRIDE;
    constexpr int SBUF_B = TN*SSTRIDE;
    constexpr int NJ = TN/16;               // j-count per warp
    const int tid  = threadIdx.x;
    const int lane = tid & 31, wid = tid >> 5;
    const int wm = (wid >> 1) * 64, wn = (wid & 1) * (TN/2);
    const int g = lane >> 2, t = lane & 3;
    const size_t row0 = (size_t)blockIdx.y * 128;
    const size_t col0 = (size_t)blockIdx.x * TN;

    const int lr = tid >> 3;
    const int lk = (tid & 7) * 4;

    const float* Aptr = A + (row0 + lr) * K + lk;
    const float* Bptr = Bm + (col0 + lr) * K + lk;
    const u32 asb0 = smem_u32(sm);
    const u32 dst_off = (u32)(lr * SSTRIDE + lk) * 4;

    float c[4][NJ][4];
    #pragma unroll
    for (int i = 0; i < 4; i++)
        #pragma unroll
        for (int j = 0; j < NJ; j++)
            #pragma unroll
            for (int f = 0; f < 4; f++) c[i][j][f] = 0.f;

    const int KT = K >> 5;

    {
        u32 ad = asb0 + dst_off;
        u32 bd = asb0 + 2*SBUF_A*4 + dst_off;
        #pragma unroll
        for (int it = 0; it < 8; it++)
            CP16(ad + it*16*SSTRIDE*4, Aptr + (size_t)it*16*K);
        #pragma unroll
        for (int it = 0; it < TN/16; it++)
            CP16(bd + it*16*SSTRIDE*4, Bptr + (size_t)it*16*K);
        CP_COMMIT();
    }

    int buf = 0;
    for (int kt = 0; kt < KT; kt++) {
        CP_WAIT0();
        __syncthreads();
        if (kt + 1 < KT) {
            int k0 = (kt + 1) << 5;
            u32 ad = asb0 + (buf^1)*SBUF_A*4 + dst_off;
            u32 bd = asb0 + (2*SBUF_A + (buf^1)*SBUF_B)*4 + dst_off;
            #pragma unroll
            for (int it = 0; it < 8; it++)
                CP16(ad + it*16*SSTRIDE*4, Aptr + k0 + (size_t)it*16*K);
            #pragma unroll
            for (int it = 0; it < TN/16; it++)
                CP16(bd + it*16*SSTRIDE*4, Bptr + k0 + (size_t)it*16*K);
            CP_COMMIT();
        }
        const float* As_ = sm + buf*SBUF_A;
        const float* Bs_ = sm + 2*SBUF_A + buf*SBUF_B;
        #pragma unroll
        for (int ks = 0; ks < 4; ks++) {
            const int k8 = ks * 8;
            u32 a[4][4], b[NJ][2];
            #pragma unroll
            for (int i = 0; i < 4; i++) {
                int m0 = wm + 16*i;
                a[i][0] = __float_as_uint(As_[(m0+g  )*SSTRIDE + k8 + t  ]);
                a[i][1] = __float_as_uint(As_[(m0+g+8)*SSTRIDE + k8 + t  ]);
                a[i][2] = __float_as_uint(As_[(m0+g  )*SSTRIDE + k8 + t+4]);
                a[i][3] = __float_as_uint(As_[(m0+g+8)*SSTRIDE + k8 + t+4]);
            }
            #pragma unroll
            for (int j = 0; j < NJ; j++) {
                int n0 = wn + 8*j;
                b[j][0] = __float_as_uint(Bs_[(n0+g)*SSTRIDE + k8 + t  ]);
                b[j][1] = __float_as_uint(Bs_[(n0+g)*SSTRIDE + k8 + t+4]);
            }
            #pragma unroll
            for (int i = 0; i < 4; i++)
                #pragma unroll
                for (int j = 0; j < NJ; j++)
                    MMA_TF32(c[i][j], a[i], b[j]);
        }
        buf ^= 1;
    }

    #pragma unroll
    for (int i = 0; i < 4; i++) {
        size_t r0 = row0 + wm + 16*i + g;
        size_t r1 = r0 + 8;
        #pragma unroll
        for (int j = 0; j < NJ; j++) {
            int cb = (int)col0 + wn + 8*j + 2*t;
            float b0 = bias[cb], b1 = bias[cb+1];
            float v0 = c[i][j][0] + b0, v1 = c[i][j][1] + b1;
            float v2 = c[i][j][2] + b0, v3 = c[i][j][3] + b1;
            if (EPI == EPI_RES) {
                float2 ra = *(const float2*)&res[r0*N + cb];
                float2 rb = *(const float2*)&res[r1*N + cb];
                v0 += ra.x; v1 += ra.y; v2 += rb.x; v3 += rb.y;
            }
            if (EPI == EPI_GELU) {
                v0 = f2tf32(gelu_f(v0)); v1 = f2tf32(gelu_f(v1));
                v2 = f2tf32(gelu_f(v2)); v3 = f2tf32(gelu_f(v3));
            }
            if (EPI == EPI_RND) {
                v0 = f2tf32(v0); v1 = f2tf32(v1);
                v2 = f2tf32(v2); v3 = f2tf32(v3);
            }
            if (EPI == EPI_PE) {
                float f0 = __expf((float)(cb & ~1)  * (1.f/(float)D_) * -9.210340371976184f);
                float f1 = __expf((float)((cb+1)&~1)* (1.f/(float)D_) * -9.210340371976184f);
                {
                    int bb_ = (int)(r0 >> 10), nn = (int)(r0 & 1023);
                    float pos = (float)(nn + 1);
                    float s0, c0s, s1, c1s;
                    __sincosf(pos * f0, &s0, &c0s);
                    __sincosf(pos * f1, &s1, &c1s);
                    float pe0 = (cb & 1) ? c0s : s0;
                    float pe1 = ((cb+1) & 1) ? c1s : s1;
                    size_t o = ((size_t)bb_*SEQ_ + nn + 1)*D_ + cb;
                    *(float2*)&C[o] = make_float2(v0 + pe0, v1 + pe1);
                }
                {
                    int bb_ = (int)(r1 >> 10), nn = (int)(r1 & 1023);
                    float pos = (float)(nn + 1);
                    float s0, c0s, s1, c1s;
                    __sincosf(pos * f0, &s0, &c0s);
                    __sincosf(pos * f1, &s1, &c1s);
                    float pe0 = (cb & 1) ? c0s : s0;
                    float pe1 = ((cb+1) & 1) ? c1s : s1;
                    size_t o = ((size_t)bb_*SEQ_ + nn + 1)*D_ + cb;
                    *(float2*)&C[o] = make_float2(v2 + pe0, v3 + pe1);
                }
            } else {
                *(float2*)&C[r0*N + cb] = make_float2(v0, v1);
                *(float2*)&C[r1*N + cb] = make_float2(v2, v3);
            }
        }
    }
}

// ---------------- fused flash attention (double-buffered, occ 1) -------------
#define FS_STRIDE 68
#define FV_STRIDE 72
#define FK_OFF   (128*FS_STRIDE)
#define FK_TILE  (128*FS_STRIDE)
#define FV_OFF   (3*128*FS_STRIDE)
#define FV_TILE  (128*FV_STRIDE)
#define FS_TOTALF (3*128*FS_STRIDE + 2*128*FV_STRIDE)  // 44544 floats

__global__ __launch_bounds__(256, 1)
void flash_k(const float* __restrict__ qkv, float* __restrict__ attn)
{
    extern __shared__ float sm[];
    __shared__ float rsx[4][32];
    const int tid  = threadIdx.x;
    const int lane = tid & 31, wid = tid >> 5;
    const int wr = wid >> 1, wc = wid & 1;
    const int wm = wr*32, wn = wc*64;
    const int g = lane >> 2, t = lane & 3;
    const int q0 = blockIdx.x * 128;
    const int bh = blockIdx.y, b = bh / H_, h = bh % H_;
    const float* Qb = qkv + (size_t)b*SEQ_*QKV_N + h*HD_;
    const float* Kb = Qb + D_;
    const float* Vb = Qb + 2*D_;

    const int lr = tid >> 3;
    const int kc = (tid & 7) * 8;
    const u32 sb = smem_u32(sm);

    #pragma unroll
    for (int it = 0; it < 4; it++) {
        int r = lr + 32*it;
        int q = min(q0 + r, SEQ_-1);
        const float4* qa = (const float4*)(Qb + (size_t)q*QKV_N + kc);
        float4 a0 = qa[0], a1 = qa[1];
        a0.x *= 0.125f; a0.y *= 0.125f; a0.z *= 0.125f; a0.w *= 0.125f;
        a1.x *= 0.125f; a1.y *= 0.125f; a1.z *= 0.125f; a1.w *= 0.125f;
        *(float4*)(sm + r*FS_STRIDE + kc)     = a0;
        *(float4*)(sm + r*FS_STRIDE + kc + 4) = a1;
    }

    {
        #pragma unroll
        for (int it = 0; it < 4; it++) {
            int r = lr + 32*it;
            int j = min(r, SEQ_-1);
            u32 dK = (u32)(FK_OFF + r*FS_STRIDE + kc)*4;
            u32 dV = (u32)(FV_OFF + r*FV_STRIDE + kc)*4;
            CP16(sb + dK,      Kb + (size_t)j*QKV_N + kc);
            CP16(sb + dK + 16, Kb + (size_t)j*QKV_N + kc + 4);
            CP16(sb + dV,      Vb + (size_t)j*QKV_N + kc);
            CP16(sb + dV + 16, Vb + (size_t)j*QKV_N + kc + 4);
        }
        CP_COMMIT();
    }

    float c2[2][8][4];
    #pragma unroll
    for (int i = 0; i < 2; i++)
        #pragma unroll
        for (int j = 0; j < 8; j++)
            #pragma unroll
            for (int f = 0; f < 4; f++) c2[i][j][f] = 0.f;
    float rs[2][2] = {{0.f,0.f},{0.f,0.f}};

    int buf = 0;
    for (int kb = 0; kb < 9; kb++) {
        CP_WAIT0();
        __syncthreads();
        if (kb + 1 < 9) {
            int nb = buf ^ 1;
            #pragma unroll
            for (int it = 0; it < 4; it++) {
                int r = lr + 32*it;
                int j = min((kb+1)*128 + r, SEQ_-1);
                u32 dK = (u32)(FK_OFF + nb*FK_TILE + r*FS_STRIDE + kc)*4;
                u32 dV = (u32)(FV_OFF + nb*FV_TILE + r*FV_STRIDE + kc)*4;
                CP16(sb + dK,      Kb + (size_t)j*QKV_N + kc);
                CP16(sb + dK + 16, Kb + (size_t)j*QKV_N + kc + 4);
                CP16(sb + dV,      Vb + (size_t)j*QKV_N + kc);
                CP16(sb + dV + 16, Vb + (size_t)j*QKV_N + kc + 4);
            }
            CP_COMMIT();
        }

        const float* Ksb = sm + FK_OFF + buf*FK_TILE;
        const float* Vsb = sm + FV_OFF + buf*FV_TILE;

        float c[2][8][4];
        #pragma unroll
        for (int i = 0; i < 2; i++)
            #pragma unroll
            for (int j = 0; j < 8; j++)
                #pragma unroll
                for (int f = 0; f < 4; f++) c[i][j][f] = 0.f;

        #pragma unroll
        for (int ks = 0; ks < 8; ks++) {
            const int k8 = ks*8;
            u32 a[2][4], bb[8][2];
            #pragma unroll
            for (int i = 0; i < 2; i++) {
                int m0 = wm + 16*i;
                a[i][0] = __float_as_uint(sm[(m0+g  )*FS_STRIDE + k8 + t  ]);
                a[i][1] = __float_as_uint(sm[(m0+g+8)*FS_STRIDE + k8 + t  ]);
                a[i][2] = __float_as_uint(sm[(m0+g  )*FS_STRIDE + k8 + t+4]);
                a[i][3] = __float_as_uint(sm[(m0+g+8)*FS_STRIDE + k8 + t+4]);
            }
            #pragma unroll
            for (int j = 0; j < 8; j++) {
                int n0 = wn + 8*j;
                bb[j][0] = __float_as_uint(Ksb[(n0+g)*FS_STRIDE + k8 + t  ]);
                bb[j][1] = __float_as_uint(Ksb[(n0+g)*FS_STRIDE + k8 + t+4]);
            }
            #pragma unroll
            for (int i = 0; i < 2; i++)
                #pragma unroll
                for (int j = 0; j < 8; j++)
                    MMA_TF32(c[i][j], a[i], bb[j]);
        }

        #pragma unroll
        for (int i = 0; i < 2; i++) {
            #pragma unroll
            for (int j = 0; j < 8; j++) {
                int colb = kb*128 + wn + 8*j + 2*t;
                float p0 = (colb   < SEQ_) ? f2tf32(__expf(c[i][j][0])) : 0.f;
                float p1 = (colb+1 < SEQ_) ? f2tf32(__expf(c[i][j][1])) : 0.f;
                float p2 = (colb   < SEQ_) ? f2tf32(__expf(c[i][j][2])) : 0.f;
                float p3 = (colb+1 < SEQ_) ? f2tf32(__expf(c[i][j][3])) : 0.f;
                c[i][j][0] = p0; c[i][j][1] = p1; c[i][j][2] = p2; c[i][j][3] = p3;
                rs[i][0] += p0 + p1;
                rs[i][1] += p2 + p3;
            }
        }

        const int sL = (lane & ~3) | (t >> 1);
        const int sH = sL | 2;
        const bool odd = (t & 1);
        #pragma unroll
        for (int ks = 0; ks < 8; ks++) {
            u32 a2[2][4];
            #pragma unroll
            for (int i = 0; i < 2; i++) {
                float p0 = __shfl_sync(0xffffffffu, c[i][ks][0], sL);
                float p1 = __shfl_sync(0xffffffffu, c[i][ks][1], sL);
                float p2 = __shfl_sync(0xffffffffu, c[i][ks][2], sL);
                float p3 = __shfl_sync(0xffffffffu, c[i][ks][3], sL);
                float q0 = __shfl_sync(0xffffffffu, c[i][ks][0], sH);
                float q1 = __shfl_sync(0xffffffffu, c[i][ks][1], sH);
                float q2 = __shfl_sync(0xffffffffu, c[i][ks][2], sH);
                float q3 = __shfl_sync(0xffffffffu, c[i][ks][3], sH);
                a2[i][0] = __float_as_uint(odd ? p1 : p0);
                a2[i][1] = __float_as_uint(odd ? p3 : p2);
                a2[i][2] = __float_as_uint(odd ? q1 : q0);
                a2[i][3] = __float_as_uint(odd ? q3 : q2);
            }
            #pragma unroll
            for (int j = 0; j < 8; j++) {
                u32 bb[2];
                bb[0] = __float_as_uint(Vsb[(wn + ks*8 + t    )*FV_STRIDE + 8*j + g]);
                bb[1] = __float_as_uint(Vsb[(wn + ks*8 + t + 4)*FV_STRIDE + 8*j + g]);
                #pragma unroll
                for (int i = 0; i < 2; i++)
                    MMA_TF32(c2[i][j], a2[i], bb);
            }
        }
        buf ^= 1;
    }

    #pragma unroll
    for (int i = 0; i < 2; i++) {
        #pragma unroll
        for (int s = 0; s < 2; s++) {
            float v = rs[i][s];
            v += __shfl_xor_sync(0xffffffffu, v, 1);
            v += __shfl_xor_sync(0xffffffffu, v, 2);
            rs[i][s] = v;
        }
    }

    __syncthreads();
    if (wc == 1) {
        float* Ox = sm + wr*(32*FS_STRIDE);
        #pragma unroll
        for (int i = 0; i < 2; i++) {
            #pragma unroll
            for (int j = 0; j < 8; j++) {
                *(float2*)(Ox + (16*i+g  )*FS_STRIDE + 8*j + 2*t) = make_float2(c2[i][j][0], c2[i][j][1]);
                *(float2*)(Ox + (16*i+g+8)*FS_STRIDE + 8*j + 2*t) = make_float2(c2[i][j][2], c2[i][j][3]);
            }
        }
        if (t == 0) {
            rsx[wr][16*0+g]   = rs[0][0];
            rsx[wr][16*0+g+8] = rs[0][1];
            rsx[wr][16*1+g]   = rs[1][0];
            rsx[wr][16*1+g+8] = rs[1][1];
        }
    }
    __syncthreads();
    if (wc == 0) {
        const float* Ox = sm + wr*(32*FS_STRIDE);
        #pragma unroll
        for (int i = 0; i < 2; i++) {
            int r0 = q0 + wm + 16*i + g;
            int r1 = r0 + 8;
            float inv0 = 1.f / (rs[i][0] + rsx[wr][16*i+g]);
            float inv1 = 1.f / (rs[i][1] + rsx[wr][16*i+g+8]);
            #pragma unroll
            for (int j = 0; j < 8; j++) {
                float2 e0 = *(const float2*)(Ox + (16*i+g  )*FS_STRIDE + 8*j + 2*t);
                float2 e1 = *(const float2*)(Ox + (16*i+g+8)*FS_STRIDE + 8*j + 2*t);
                if (r0 < SEQ_) {
                    size_t o = ((size_t)b*SEQ_ + r0)*D_ + h*HD_ + 8*j + 2*t;
                    *(float2*)&attn[o] = make_float2(f2tf32((c2[i][j][0]+e0.x)*inv0),
                                                     f2tf32((c2[i][j][1]+e0.y)*inv0));
                }
                if (r1 < SEQ_) {
                    size_t o = ((size_t)b*SEQ_ + r1)*D_ + h*HD_ + 8*j + 2*t;
                    *(float2*)&attn[o] = make_float2(f2tf32((c2[i][j][2]+e1.x)*inv1),
                                                     f2tf32((c2[i][j][3]+e1.y)*inv1));
                }
            }
        }
    }
}

// ---------------- layernorm: warp per row, shfl reductions -------------------
__global__ __launch_bounds__(256)
void ln_k(const float* __restrict__ x, const float* __restrict__ g,
          const float* __restrict__ b, float* __restrict__ y)
{
    const int w    = threadIdx.x >> 5;
    const int lane = threadIdx.x & 31;
    const int row  = blockIdx.x * 8 + w;
    const float* xr = x + (size_t)row*D_;
    float v[12];
    float s = 0.f;
    #pragma unroll
    for (int i = 0; i < 12; i++) { v[i] = xr[lane + 32*i]; s += v[i]; }
    #pragma unroll
    for (int o = 16; o > 0; o >>= 1) s += __shfl_xor_sync(0xffffffffu, s, o);
    float mu = s * (1.f/D_);
    float s2 = 0.f;
    #pragma unroll
    for (int i = 0; i < 12; i++) { float d = v[i]-mu; s2 += d*d; }
    #pragma unroll
    for (int o = 16; o > 0; o >>= 1) s2 += __shfl_xor_sync(0xffffffffu, s2, o);
    float inv = rsqrtf(s2*(1.f/D_) + 1e-5f);
    float* yr = y + (size_t)row*D_;
    #pragma unroll
    for (int i = 0; i < 12; i++) {
        int c = lane + 32*i;
        yr[c] = f2tf32((v[i]-mu)*inv*g[c] + b[c]);
    }
}

// ---------------- all prep in ONE kernel (weights + image round + cls rows) --
#define T1_ (L_*QKV_N*D_)
#define T2_ (L_*D_*D_)
#define T3_ (L_*FF_*D_)
#define T4_ (L_*D_*FF_)
#define T5_ (D_*256)
#define T6_ (L_*QKV_N)
#define T7_ (B_*N_*256)
#define T8_ (B_*D_)
__global__ void prep_k(const float* __restrict__ wq, const float* __restrict__ wk,
                       const float* __restrict__ wv, const float* __restrict__ bq,
                       const float* __restrict__ bk, const float* __restrict__ bv,
                       const float* __restrict__ wo, const float* __restrict__ w1,
                       const float* __restrict__ w2, const float* __restrict__ pat,
                       const float* __restrict__ images, const float* __restrict__ cls,
                       float* __restrict__ qkvT, float* __restrict__ woT,
                       float* __restrict__ w1T, float* __restrict__ w2T,
                       float* __restrict__ patT, float* __restrict__ pb,
                       float* __restrict__ img, float* __restrict__ x)
{
    int idx = blockIdx.x*blockDim.x + threadIdx.x;
    if (idx < T1_) {
        int k = idx % D_; int r = idx / D_; int n = r % QKV_N; int l = r / QKV_N;
        int sec = n / D_, jj = n % D_, h = jj >> 6, e = jj & 63;
        const float* w = (sec == 0) ? wq : (sec == 1) ? wk : wv;
        qkvT[idx] = f2tf32(w[(((size_t)l*H_ + h)*D_ + k)*HD_ + e]);
    } else if (idx < T1_+T2_) {
        int i = idx - T1_;
        int k = i % D_; int r = i / D_; int n = r % D_; int l = r / D_;
        woT[i] = f2tf32(wo[((size_t)l*D_ + k)*D_ + n]);
    } else if (idx < T1_+T2_+T3_) {
        int i = idx - (T1_+T2_);
        int k = i % D_; int r = i / D_; int n = r % FF_; int l = r / FF_;
        w1T[i] = f2tf32(w1[((size_t)l*D_ + k)*FF_ + n]);
    } else if (idx < T1_+T2_+T3_+T4_) {
        int i = idx - (T1_+T2_+T3_);
        int k = i % FF_; int r = i / FF_; int n = r % D_; int l = r / D_;
        w2T[i] = f2tf32(w2[((size_t)l*FF_ + k)*D_ + n]);
    } else if (idx < T1_+T2_+T3_+T4_+T5_) {
        int i = idx - (T1_+T2_+T3_+T4_);
        int k = i % 256; int n = i / 256;
        patT[i] = f2tf32(pat[(size_t)k*D_ + n]);
    } else if (idx < T1_+T2_+T3_+T4_+T5_+T6_) {
        int i = idx - (T1_+T2_+T3_+T4_+T5_);
        int n = i % QKV_N; int l = i / QKV_N;
        int sec = n / D_, jj = n % D_, h = jj >> 6, e = jj & 63;
        const float* bb = (sec == 0) ? bq : (sec == 1) ? bk : bv;
        pb[i] = bb[((size_t)l*H_ + h)*HD_ + e];
    } else if (idx < T1_+T2_+T3_+T4_+T5_+T6_+T7_) {
        int i = idx - (T1_+T2_+T3_+T4_+T5_+T6_);
        img[i] = f2tf32(images[i]);
    } else if (idx < T1_+T2_+T3_+T4_+T5_+T6_+T7_+T8_) {
        int i = idx - (T1_+T2_+T3_+T4_+T5_+T6_+T7_);
        int d = i % D_; int b = i / D_;
        x[(size_t)b*SEQ_*D_ + d] = cls[d] + ((d & 1) ? 1.f : 0.f);
    }
}

// ---------------- fused head: logits (NC=2) + deconv upsample ----------------
__global__ __launch_bounds__(256)
void head_k(const float* __restrict__ x, const float* __restrict__ cw,
            const float* __restrict__ cb, const float* __restrict__ dw,
            const float* __restrict__ db, float* __restrict__ out)
{
    const int w    = threadIdx.x >> 5;
    const int lane = threadIdx.x & 31;
    const int tok  = blockIdx.x * 8 + w;
    const int b = tok >> 10, n = tok & 1023;
    const float* xr = x + ((size_t)b*SEQ_ + n + 1)*D_;

    float s0 = 0.f, s1 = 0.f;
    #pragma unroll
    for (int i = 0; i < 12; i++) {
        int d = lane + 32*i;
        float xv = xr[d];
        s0 += xv * cw[d*NC_];
        s1 += xv * cw[d*NC_ + 1];
    }
    #pragma unroll
    for (int o = 16; o > 0; o >>= 1) {
        s0 += __shfl_xor_sync(0xffffffffu, s0, o);
        s1 += __shfl_xor_sync(0xffffffffu, s1, o);
    }
    float z0 = s0 + cb[0], z1 = s1 + cb[1];

    #pragma unroll
    for (int o = 0; o < NC_; o++) {
        size_t base = ((size_t)(b*NC_ + o) * (N_*16) + n*16) * 16;
        float dbv = db[o];
        #pragma unroll
        for (int i = 0; i < 8; i++) {
            int p = lane + 32*i;
            out[base + p] = dbv + z0*dw[o*256 + p] + z1*dw[(NC_ + o)*256 + p];
        }
    }
}

// ---------------- launch ------------------------------------------------------
extern "C" void kernel_launch(void* const* d_in, const int* in_sizes, int n_in,
                              void* d_out, int out_size)
{
    const float* images  = (const float*)d_in[0];
    const float* patch_w = (const float*)d_in[2];
    const float* patch_b = (const float*)d_in[3];
    const float* cls_tok = (const float*)d_in[4];
    const float* ln1_g   = (const float*)d_in[5];
    const float* ln1_b   = (const float*)d_in[6];
    const float* wq      = (const float*)d_in[7];
    const float* bq      = (const float*)d_in[8];
    const float* wk      = (const float*)d_in[9];
    const float* bk      = (const float*)d_in[10];
    const float* wv      = (const float*)d_in[11];
    const float* bv      = (const float*)d_in[12];
    const float* wo      = (const float*)d_in[13];
    const float* bo      = (const float*)d_in[14];
    const float* ln2_g   = (const float*)d_in[15];
    const float* ln2_b   = (const float*)d_in[16];
    const float* w1      = (const float*)d_in[17];
    const float* b1      = (const float*)d_in[18];
    const float* w2      = (const float*)d_in[19];
    const float* b2      = (const float*)d_in[20];
    const float* cls_w   = (const float*)d_in[21];
    const float* cls_b   = (const float*)d_in[22];
    const float* dc_w    = (const float*)d_in[23];
    const float* dc_b    = (const float*)d_in[24];
    float* out = (float*)d_out;

    float *x, *h, *qkv, *attn, *mlp, *pb;
    float *qkvT, *woT, *w1T, *w2T, *patT, *img;
    cudaGetSymbolAddress((void**)&x,    g_x);
    cudaGetSymbolAddress((void**)&h,    g_h);
    cudaGetSymbolAddress((void**)&qkv,  g_qkv);
    cudaGetSymbolAddress((void**)&attn, g_attn);
    cudaGetSymbolAddress((void**)&mlp,  g_mlp);
    cudaGetSymbolAddress((void**)&pb,   g_pb);
    cudaGetSymbolAddress((void**)&qkvT, g_qkvT);
    cudaGetSymbolAddress((void**)&woT,  g_woT);
    cudaGetSymbolAddress((void**)&w1T,  g_w1T);
    cudaGetSymbolAddress((void**)&w2T,  g_w2T);
    cudaGetSymbolAddress((void**)&patT, g_patT);
    cudaGetSymbolAddress((void**)&img,  g_img);

    const int SMEM_G128 = (4*128)*SSTRIDE*4;        // 73728 B
    const int SMEM_G64  = (2*128 + 2*64)*SSTRIDE*4; // 55296 B
    const int SMEM_F    = FS_TOTALF*4;              // 178176 B
    cudaFuncSetAttribute(gemm4_k<EPI_RND,128>,  cudaFuncAttributeMaxDynamicSharedMemorySize, SMEM_G128);
    cudaFuncSetAttribute(gemm4_k<EPI_GELU,128>, cudaFuncAttributeMaxDynamicSharedMemorySize, SMEM_G128);
    cudaFuncSetAttribute(gemm4_k<EPI_PE,128>,   cudaFuncAttributeMaxDynamicSharedMemorySize, SMEM_G128);
    cudaFuncSetAttribute(gemm4_k<EPI_RES,64>,   cudaFuncAttributeMaxDynamicSharedMemorySize, SMEM_G64);
    cudaFuncSetAttribute(flash_k, cudaFuncAttributeMaxDynamicSharedMemorySize, SMEM_F);

    {
        int total = T1_+T2_+T3_+T4_+T5_+T6_+T7_+T8_;
        prep_k<<<(total + 255)/256, 256>>>(wq, wk, wv, bq, bk, bv, wo, w1, w2,
                                           patch_w, images, cls_tok,
                                           qkvT, woT, w1T, w2T, patT, pb, img, x);
    }
    {
        dim3 g(D_/128, (B_*N_)/128);
        gemm4_k<EPI_PE,128><<<g, 128, SMEM_G128>>>(img, patT, patch_b, nullptr, x,
                                                   B_*N_, D_, 256);
    }

    dim3 gq(QKV_N/128, ROWSP_/128);
    dim3 go64(D_/64,   ROWSP_/128);     // 6 x 65 = 390 CTAs
    dim3 g1(FF_/128,   ROWSP_/128);
    dim3 gf(SP_/128, B_*H_);

    for (int l = 0; l < L_; l++) {
        ln_k<<<ROWS_/8, 256>>>(x, ln1_g + l*D_, ln1_b + l*D_, h);
        gemm4_k<EPI_RND,128><<<gq, 128, SMEM_G128>>>(h, qkvT + (size_t)l*QKV_N*D_,
                                                     pb + l*QKV_N, nullptr,
                                                     qkv, ROWSP_, QKV_N, D_);
        flash_k<<<gf, 256, SMEM_F>>>(qkv, attn);
        gemm4_k<EPI_RES,64><<<go64, 128, SMEM_G64>>>(attn, woT + (size_t)l*D_*D_,
                                                     bo + l*D_, x,
                                                     x, ROWSP_, D_, D_);
        ln_k<<<ROWS_/8, 256>>>(x, ln2_g + l*D_, ln2_b + l*D_, h);
        gemm4_k<EPI_GELU,128><<<g1, 128, SMEM_G128>>>(h, w1T + (size_t)l*FF_*D_,
                                                      b1 + l*FF_, nullptr,
                                                      mlp, ROWSP_, FF_, D_);
        gemm4_k<EPI_RES,64><<<go64, 128, SMEM_G64>>>(mlp, w2T + (size_t)l*D_*FF_,
                                                     b2 + l*D_, x,
                                                     x, ROWSP_, D_, FF_);
    }

    head_k<<<(B_*N_)/8, 256>>>(x, cls_w, cls_b, dc_w, dc_b, out);
    (void)in_sizes; (void)n_in; (void)out_size;
}